// round 13
// baseline (speedup 1.0000x reference)
#include <cuda_runtime.h>
#include <cuda_bf16.h>
#include <math.h>
#include <stdint.h>

#define DT_STEP 0.1f
#define EPS_TAU 1e-6f

constexpr int B = 256, T = 512, I = 64, H = 512, O = 64;
constexpr int GRID = 144;   // 128 layer CTAs + 16 out-proj CTAs; all co-resident
constexpr int KP = H / 2;   // 256 kpairs per h row
constexpr int NKT = KP / 8; // 32 k16-tiles per h row
constexpr int GSZ = 18;     // CTAs per row-block group (16 main + 2 out)

// smem b32 offsets
constexpr int WA_HI = 0;        // 9216 (K=576)
constexpr int WA_LO = 9216;
constexpr int WB_HI = 18432;    // 16384 (K=1024)
constexpr int WB_LO = 34816;
constexpr int ACT = 51200;      // 2 bufs x (1024 hi + 1024 lo)
constexpr int MISC = ACT + 4096;
constexpr int SMEM_BYTES = (MISC + 128) * 4;  // 221,696 B

// Global activation planes in MMA fragment order (round-8 layout).
constexpr int HPLANE = (B / 16) * NKT * 128;    // 65536 u32
constexpr int XPLANE = (B / 16) * T * 4 * 128;

__device__ uint32_t g_h0hi[2][HPLANE], g_h0lo[2][HPLANE];
__device__ uint32_t g_h1hi[2][HPLANE], g_h1lo[2][HPLANE];
__device__ uint32_t g_pxhi[XPLANE], g_pxlo[XPLANE];
__device__ unsigned g_arr[8 * 32];  // one barrier counter per row-block, 128B apart

__global__ void k_init() {
    int idx = blockIdx.x * blockDim.x + threadIdx.x;
    if (idx < HPLANE) {
        g_h0hi[0][idx] = 0u; g_h0hi[1][idx] = 0u;
        g_h0lo[0][idx] = 0u; g_h0lo[1][idx] = 0u;
        g_h1hi[0][idx] = 0u; g_h1hi[1][idx] = 0u;
        g_h1lo[0][idx] = 0u; g_h1lo[1][idx] = 0u;
    }
    if (idx < 8 * 32) g_arr[idx] = 0u;
}

__device__ __forceinline__ uint32_t pack2(float e0, float e1) {
    uint32_t r;  // low half = e0
    asm("cvt.rn.bf16x2.f32 %0, %1, %2;" : "=r"(r) : "f"(e1), "f"(e0));
    return r;
}
__device__ __forceinline__ float bfr(float x) {
    return __bfloat162float(__float2bfloat16_rn(x));
}
__device__ __forceinline__ uint2 packpair(float e0, float e1) {
    float h0 = bfr(e0), h1 = bfr(e1);
    return make_uint2(pack2(h0, h1), pack2(e0 - h0, e1 - h1));
}

// Pre-pack x into fragment-order planes.
__global__ void k_prep(const float* __restrict__ x) {
    int n = (B / 16) * T * 4 * 32;
    for (int i = blockIdx.x * blockDim.x + threadIdx.x; i < n;
         i += gridDim.x * blockDim.x) {
        int lane = i & 31, ktx = (i >> 5) & 3, t = (i >> 7) & (T - 1), rbg = i >> 16;
        int gid = lane >> 2, tigf = lane & 3;
        int kp0 = ktx * 8 + tigf;
        const float* xb = x + (size_t)(rbg * 16 + gid) * (T * I) + t * I;
        const float* xb8 = xb + 8 * (T * I);
        float2 v0 = *(const float2*)(xb + kp0 * 2);
        float2 v1 = *(const float2*)(xb8 + kp0 * 2);
        float2 v2 = *(const float2*)(xb + (kp0 + 4) * 2);
        float2 v3 = *(const float2*)(xb8 + (kp0 + 4) * 2);
        uint2 p0 = packpair(v0.x, v0.y), p1 = packpair(v1.x, v1.y);
        uint2 p2 = packpair(v2.x, v2.y), p3 = packpair(v3.x, v3.y);
        *(uint4*)(g_pxhi + i * 4) = make_uint4(p0.x, p1.x, p2.x, p3.x);
        *(uint4*)(g_pxlo + i * 4) = make_uint4(p0.y, p1.y, p2.y, p3.y);
    }
}

__device__ __forceinline__ void mmaw(float* d, uint4 a, uint2 b) {
    asm volatile(
        "mma.sync.aligned.m16n8k16.row.col.f32.bf16.bf16.f32 "
        "{%0,%1,%2,%3},{%4,%5,%6,%7},{%8,%9},{%0,%1,%2,%3};"
        : "+f"(d[0]), "+f"(d[1]), "+f"(d[2]), "+f"(d[3])
        : "r"(a.x), "r"(a.y), "r"(a.z), "r"(a.w), "r"(b.x), "r"(b.y));
}

// Per-row-block group barrier (18 CTAs); cross-row-block state is disjoint.
__device__ __forceinline__ void gsync(int grp, unsigned& epoch) {
    epoch++;
    __syncthreads();
    __threadfence();
    if (threadIdx.x == 0) {
        atomicAdd(&g_arr[grp * 32], 1u);
        unsigned target = (unsigned)GSZ * epoch;
        while (*(volatile unsigned*)&g_arr[grp * 32] < target) {}
    }
    __syncthreads();
    __threadfence();
}

// One-time weight staging into fragment order.
__device__ void stage_wfrag(uint32_t* sm32, int hiOff, int loOff, int pairs,
                            const float* W0, int s0, int klim,
                            const float* W1, int s1) {
    for (int idx = threadIdx.x; idx < pairs; idx += 256) {
        int s = idx & 1, lane = (idx >> 1) & 31;
        int nb = (idx >> 6) & 3, ktG = idx >> 8;
        int gid = lane >> 2, tig = lane & 3;
        int n = nb * 8 + gid, k = ktG * 16 + tig * 2 + s * 8;
        const float* src; int kk;
        if (k < klim) { src = W0 + n * s0; kk = k; }
        else { src = W1 + n * s1; kk = k - klim; }
        float w0 = src[kk], w1 = src[kk + 1];
        float h0 = bfr(w0), h1 = bfr(w1);
        sm32[hiOff + idx] = pack2(h0, h1);
        sm32[loOff + idx] = pack2(w0 - h0, w1 - h1);
    }
}

__device__ __forceinline__ void stage_ld(uint4& vh, uint4& vl,
                                         const uint32_t* hp, const uint32_t* lp,
                                         int off0, int off1) {
    int tid = threadIdx.x;
    int off = ((tid >> 7) ? off1 : off0) + (tid & 127) * 4;
    vh = *(const uint4*)(hp + off);
    vl = *(const uint4*)(lp + off);
}
__device__ __forceinline__ void stage_st(uint32_t* sm, int bufIdx,
                                         uint4 vh, uint4 vl) {
    int tid = threadIdx.x;
    uint32_t* d = sm + ACT + bufIdx * 2048 + (tid >> 7) * 512 + (tid & 127) * 4;
    *(uint4*)d = vh;
    *(uint4*)(d + 1024) = vl;
}

// 4 k16-tiles of one staged chunk with EVEN/ODD accumulator split.
__device__ __forceinline__ void mma_chunk(float* accE, float* accO,
                                          const uint32_t* smact,
                                          const uint32_t* whi, const uint32_t* wlo,
                                          int ktG0, int rb, int nb, int lane) {
#pragma unroll
    for (int ktl = 0; ktl < 4; ktl++) {
        const uint32_t* a = smact + (rb * 4 + ktl) * 128 + lane * 4;
        uint4 ah = *(const uint4*)a;
        uint4 al = *(const uint4*)(a + 1024);
        int widx = (ktG0 + ktl) * 4 + nb;
        uint2 bh = *(const uint2*)(whi + (widx * 32 + lane) * 2);
        uint2 bl = *(const uint2*)(wlo + (widx * 32 + lane) * 2);
        float* d = (ktl & 1) ? accO : accE;
        mmaw(d, ah, bh);
        mmaw(d, ah, bl);
        mmaw(d, al, bh);
    }
}

// Merged-interval persistent scan; per-row-block barriers; 2-DEEP LDG prefetch.
__global__ __launch_bounds__(256, 1) void k_scan(
    const float* __restrict__ x, const float* __restrict__ Win0,
    const float* __restrict__ bin0, const float* __restrict__ A0,
    const float* __restrict__ tau0, const float* __restrict__ Win1,
    const float* __restrict__ bin1, const float* __restrict__ A1,
    const float* __restrict__ tau1, const float* __restrict__ Wout,
    const float* __restrict__ bout, float* __restrict__ out) {
    extern __shared__ uint32_t sm[];
    float* miscf = (float*)(sm + MISC);
    const int tid = threadIdx.x, bx = blockIdx.x;
    const int w = tid >> 5, lane = tid & 31;
    const int gid = lane >> 2, tig = lane & 3;
    const int rb = w & 1, nb = w >> 1;
    const bool is_main = (bx < 128);
    int row0, col0;
    if (is_main) { row0 = (bx >> 4) * 32; col0 = (bx & 15) * 32; }
    else { int idx = bx - 128; row0 = (idx >> 1) * 32; col0 = (idx & 1) * 32; }
    const int grp = row0 >> 5;  // row-block group id (0..7)

    if (is_main) {
        stage_wfrag(sm, WA_HI, WA_LO, 9216, A0 + col0 * H, H, 512,
                    Win0 + col0 * I, I);
        stage_wfrag(sm, WB_HI, WB_LO, 16384, Win1 + col0 * H, H, 512,
                    A1 + col0 * H, H);
        if (tid < 32) {
            miscf[tid] = bin0[col0 + tid];
            miscf[32 + tid] = 1.0f / (fabsf(tau0[col0 + tid]) + EPS_TAU);
            miscf[64 + tid] = bin1[col0 + tid];
            miscf[96 + tid] = 1.0f / (fabsf(tau1[col0 + tid]) + EPS_TAU);
        }
    } else {
        stage_wfrag(sm, 0, 8192, 8192, Wout + col0 * H, H, 1 << 20, Wout, H);
        if (tid < 32) miscf[tid] = bout[col0 + tid];
    }
    __syncthreads();

    const int g = row0 + rb * 16 + gid;
    const int gc = col0 + nb * 8 + tig * 2;
    const int ci = nb * 8 + tig * 2;
    const int kpw = gc >> 1;
    const int rbg0 = row0 >> 4;
    const int wrbg = rbg0 + rb;
    const int widxh = ((wrbg * NKT + (kpw >> 3)) * 32 + gid * 4 + (kpw & 3)) * 4 +
                      ((kpw >> 2) & 1) * 2;
    const int oh0 = rbg0 * NKT * 128, oh1 = (rbg0 + 1) * NKT * 128;

    float hp0[4] = {0.f, 0.f, 0.f, 0.f};
    float hp1[4] = {0.f, 0.f, 0.f, 0.f};
    unsigned epoch = 0;

    for (int t = 0; t < T + 2; t++) {
        const int prh0 = (t - 1) & 1;  // h0(t-1)
        const int pwh0 = t & 1;        // h0(t)
        const int prh1 = t & 1;        // h1(t-2)
        const int pwh1 = (t - 1) & 1;  // h1(t-1)
        const bool doA = (t < T), doB = (t >= 1 && t <= T);

        if (is_main) {
            if (doA || doB) {
                const uint32_t* h0h = g_h0hi[prh0];
                const uint32_t* h0l = g_h0lo[prh0];
                const uint32_t* h1h = g_h1hi[prh1];
                const uint32_t* h1l = g_h1lo[prh1];
                const int tx = doA ? t : 0;
                const int ox0 = (rbg0 * T + tx) * 512, ox1 = ((rbg0 + 1) * T + tx) * 512;
                float accAE[4] = {0.f, 0.f, 0.f, 0.f};
                float accAO[4] = {0.f, 0.f, 0.f, 0.f};
                float accBE[4] = {0.f, 0.f, 0.f, 0.f};
                float accBO[4] = {0.f, 0.f, 0.f, 0.f};

                auto srcld = [&](uint4& vh, uint4& vl, int c) {
                    if (c < 8) stage_ld(vh, vl, h0h, h0l, oh0 + c * 512, oh1 + c * 512);
                    else if (c == 8) stage_ld(vh, vl, g_pxhi, g_pxlo, ox0, ox1);
                    else stage_ld(vh, vl, h1h, h1l, oh0 + (c - 9) * 512,
                                  oh1 + (c - 9) * 512);
                };

                uint4 vh[2], vl[2];
                srcld(vh[0], vl[0], 0);
                srcld(vh[1], vl[1], 1);
                stage_st(sm, 0, vh[0], vl[0]);
#pragma unroll 1
                for (int c = 0; c < 17; c++) {
                    __syncthreads();
                    if (c + 2 < 17) srcld(vh[c & 1], vl[c & 1], c + 2);
                    const uint32_t* ab = sm + ACT + (c & 1) * 2048;
                    if (c < 8) {
                        if (doA) mma_chunk(accAE, accAO, ab, sm + WA_HI, sm + WA_LO,
                                           c * 4, rb, nb, lane);
                        if (doB) mma_chunk(accBE, accBO, ab, sm + WB_HI, sm + WB_LO,
                                           c * 4, rb, nb, lane);
                    } else if (c == 8) {
                        if (doA) mma_chunk(accAE, accAO, ab, sm + WA_HI, sm + WA_LO,
                                           32, rb, nb, lane);
                    } else {
                        if (doB) mma_chunk(accBE, accBO, ab, sm + WB_HI, sm + WB_LO,
                                           32 + (c - 9) * 4, rb, nb, lane);
                    }
                    if (c + 1 < 17)
                        stage_st(sm, (c + 1) & 1, vh[(c + 1) & 1], vl[(c + 1) & 1]);
                    if (c == 8 && doA) {
                        // early epilogue A: finish h0(t); overlap stores with B chunks
                        float b0v = miscf[ci], b1v = miscf[ci + 1];
                        float i0 = miscf[32 + ci], i1 = miscf[32 + ci + 1];
                        float a0 = accAE[0] + accAO[0], a1 = accAE[1] + accAO[1];
                        float a2 = accAE[2] + accAO[2], a3 = accAE[3] + accAO[3];
                        hp0[0] += DT_STEP * i0 * (tanhf(a0 + b0v) - hp0[0]);
                        hp0[1] += DT_STEP * i1 * (tanhf(a1 + b1v) - hp0[1]);
                        hp0[2] += DT_STEP * i0 * (tanhf(a2 + b0v) - hp0[2]);
                        hp0[3] += DT_STEP * i1 * (tanhf(a3 + b1v) - hp0[3]);
                        uint2 u0 = packpair(hp0[0], hp0[1]);
                        uint2 u1 = packpair(hp0[2], hp0[3]);
                        *(uint2*)(g_h0hi[pwh0] + widxh) = make_uint2(u0.x, u1.x);
                        *(uint2*)(g_h0lo[pwh0] + widxh) = make_uint2(u0.y, u1.y);
                    }
                }
                if (doB) {
                    float b0v = miscf[64 + ci], b1v = miscf[64 + ci + 1];
                    float i0 = miscf[96 + ci], i1 = miscf[96 + ci + 1];
                    float a0 = accBE[0] + accBO[0], a1 = accBE[1] + accBO[1];
                    float a2 = accBE[2] + accBO[2], a3 = accBE[3] + accBO[3];
                    hp1[0] += DT_STEP * i0 * (tanhf(a0 + b0v) - hp1[0]);
                    hp1[1] += DT_STEP * i1 * (tanhf(a1 + b1v) - hp1[1]);
                    hp1[2] += DT_STEP * i0 * (tanhf(a2 + b0v) - hp1[2]);
                    hp1[3] += DT_STEP * i1 * (tanhf(a3 + b1v) - hp1[3]);
                    uint2 u0 = packpair(hp1[0], hp1[1]);
                    uint2 u1 = packpair(hp1[2], hp1[3]);
                    *(uint2*)(g_h1hi[pwh1] + widxh) = make_uint2(u0.x, u1.x);
                    *(uint2*)(g_h1lo[pwh1] + widxh) = make_uint2(u0.y, u1.y);
                }
            }
        } else if (t >= 2) {
            // y(t-2) = h1(t-2) @ Wout^T + bout
            const uint32_t* hp = g_h1hi[t & 1];
            const uint32_t* lp = g_h1lo[t & 1];
            float accE[4] = {0.f, 0.f, 0.f, 0.f};
            float accO[4] = {0.f, 0.f, 0.f, 0.f};
            uint4 vh[2], vl[2];
            stage_ld(vh[0], vl[0], hp, lp, oh0, oh1);
            stage_ld(vh[1], vl[1], hp, lp, oh0 + 512, oh1 + 512);
            stage_st(sm, 0, vh[0], vl[0]);
#pragma unroll 1
            for (int c = 0; c < 8; c++) {
                __syncthreads();
                if (c + 2 < 8) stage_ld(vh[c & 1], vl[c & 1], hp, lp,
                                        oh0 + (c + 2) * 512, oh1 + (c + 2) * 512);
                mma_chunk(accE, accO, sm + ACT + (c & 1) * 2048, sm + 0, sm + 8192,
                          c * 4, rb, nb, lane);
                if (c + 1 < 8)
                    stage_st(sm, (c + 1) & 1, vh[(c + 1) & 1], vl[(c + 1) & 1]);
            }
            float b0v = miscf[ci], b1v = miscf[ci + 1];
            *(float2*)(out + g * (T * O) + (t - 2) * O + gc) =
                make_float2(accE[0] + accO[0] + b0v, accE[1] + accO[1] + b1v);
            *(float2*)(out + (g + 8) * (T * O) + (t - 2) * O + gc) =
                make_float2(accE[2] + accO[2] + b0v, accE[3] + accO[3] + b1v);
        }
        gsync(grp, epoch);
    }
}

extern "C" void kernel_launch(void* const* d_in, const int* in_sizes, int n_in,
                              void* d_out, int out_size) {
    const float* x    = (const float*)d_in[0];
    const float* Win0 = (const float*)d_in[1];
    const float* bin0 = (const float*)d_in[2];
    const float* A0   = (const float*)d_in[3];
    const float* tau0 = (const float*)d_in[4];
    const float* Win1 = (const float*)d_in[5];
    const float* bin1 = (const float*)d_in[6];
    const float* A1   = (const float*)d_in[7];
    const float* tau1 = (const float*)d_in[8];
    const float* Wout = (const float*)d_in[9];
    const float* bout = (const float*)d_in[10];
    float* out = (float*)d_out;

    cudaFuncSetAttribute(k_scan, cudaFuncAttributeMaxDynamicSharedMemorySize,
                         SMEM_BYTES);

    k_init<<<(HPLANE + 255) / 256, 256>>>();
    k_prep<<<512, 256>>>(x);
    k_scan<<<GRID, 256, SMEM_BYTES>>>(x, Win0, bin0, A0, tau0, Win1, bin1, A1,
                                      tau1, Wout, bout, out);
}

// round 14
// speedup vs baseline: 1.7562x; 1.7562x over previous
#include <cuda_runtime.h>
#include <cuda_bf16.h>
#include <math.h>
#include <stdint.h>

#define DT_STEP 0.1f
#define EPS_TAU 1e-6f

constexpr int B = 256, T = 512, I = 64, H = 512, O = 64;
constexpr int GRID = 144;   // 128 layer CTAs + 16 out-proj CTAs; all co-resident
constexpr int KP = H / 2;   // 256 kpairs per h row
constexpr int NKT = KP / 8; // 32 k16-tiles per h row
constexpr int GSZ = 18;     // CTAs per row-block group (16 main + 2 out)

// smem b32 offsets
constexpr int WA_HI = 0;        // 9216 (K=576)
constexpr int WA_LO = 9216;
constexpr int WB_HI = 18432;    // 16384 (K=1024)
constexpr int WB_LO = 34816;
constexpr int ACT = 51200;      // 2 bufs x (1024 hi + 1024 lo)
constexpr int MISC = ACT + 4096;
constexpr int SMEM_BYTES = (MISC + 128) * 4;  // 221,696 B

// Global activation planes in MMA fragment order (round-8 layout).
constexpr int HPLANE = (B / 16) * NKT * 128;    // 65536 u32
constexpr int XPLANE = (B / 16) * T * 4 * 128;

__device__ uint32_t g_h0hi[2][HPLANE], g_h0lo[2][HPLANE];
__device__ uint32_t g_h1hi[2][HPLANE], g_h1lo[2][HPLANE];
__device__ uint32_t g_pxhi[XPLANE], g_pxlo[XPLANE];
__device__ unsigned g_arr[8 * 32];  // one barrier counter per row-block, 128B apart

__global__ void k_init() {
    int idx = blockIdx.x * blockDim.x + threadIdx.x;
    if (idx < HPLANE) {
        g_h0hi[0][idx] = 0u; g_h0hi[1][idx] = 0u;
        g_h0lo[0][idx] = 0u; g_h0lo[1][idx] = 0u;
        g_h1hi[0][idx] = 0u; g_h1hi[1][idx] = 0u;
        g_h1lo[0][idx] = 0u; g_h1lo[1][idx] = 0u;
    }
    if (idx < 8 * 32) g_arr[idx] = 0u;
}

__device__ __forceinline__ uint32_t pack2(float e0, float e1) {
    uint32_t r;  // low half = e0
    asm("cvt.rn.bf16x2.f32 %0, %1, %2;" : "=r"(r) : "f"(e1), "f"(e0));
    return r;
}
__device__ __forceinline__ float bfr(float x) {
    return __bfloat162float(__float2bfloat16_rn(x));
}
__device__ __forceinline__ uint2 packpair(float e0, float e1) {
    float h0 = bfr(e0), h1 = bfr(e1);
    return make_uint2(pack2(h0, h1), pack2(e0 - h0, e1 - h1));
}

// Pre-pack x into fragment-order planes.
__global__ void k_prep(const float* __restrict__ x) {
    int n = (B / 16) * T * 4 * 32;
    for (int i = blockIdx.x * blockDim.x + threadIdx.x; i < n;
         i += gridDim.x * blockDim.x) {
        int lane = i & 31, ktx = (i >> 5) & 3, t = (i >> 7) & (T - 1), rbg = i >> 16;
        int gid = lane >> 2, tigf = lane & 3;
        int kp0 = ktx * 8 + tigf;
        const float* xb = x + (size_t)(rbg * 16 + gid) * (T * I) + t * I;
        const float* xb8 = xb + 8 * (T * I);
        float2 v0 = *(const float2*)(xb + kp0 * 2);
        float2 v1 = *(const float2*)(xb8 + kp0 * 2);
        float2 v2 = *(const float2*)(xb + (kp0 + 4) * 2);
        float2 v3 = *(const float2*)(xb8 + (kp0 + 4) * 2);
        uint2 p0 = packpair(v0.x, v0.y), p1 = packpair(v1.x, v1.y);
        uint2 p2 = packpair(v2.x, v2.y), p3 = packpair(v3.x, v3.y);
        *(uint4*)(g_pxhi + i * 4) = make_uint4(p0.x, p1.x, p2.x, p3.x);
        *(uint4*)(g_pxlo + i * 4) = make_uint4(p0.y, p1.y, p2.y, p3.y);
    }
}

__device__ __forceinline__ void mmaw(float* d, uint4 a, uint2 b) {
    asm volatile(
        "mma.sync.aligned.m16n8k16.row.col.f32.bf16.bf16.f32 "
        "{%0,%1,%2,%3},{%4,%5,%6,%7},{%8,%9},{%0,%1,%2,%3};"
        : "+f"(d[0]), "+f"(d[1]), "+f"(d[2]), "+f"(d[3])
        : "r"(a.x), "r"(a.y), "r"(a.z), "r"(a.w), "r"(b.x), "r"(b.y));
}

// Per-row-block group barrier (18 CTAs). Staging loads bypass L1 (__ldcg),
// so only the PRE-barrier publish fence is needed; no post-barrier L1 flush.
__device__ __forceinline__ void gsync(int grp, unsigned& epoch) {
    epoch++;
    __syncthreads();
    __threadfence();
    if (threadIdx.x == 0) {
        atomicAdd(&g_arr[grp * 32], 1u);
        unsigned target = (unsigned)GSZ * epoch;
        while (*(volatile unsigned*)&g_arr[grp * 32] < target) {}
    }
    __syncthreads();
}

// One-time weight staging into fragment order.
__device__ void stage_wfrag(uint32_t* sm32, int hiOff, int loOff, int pairs,
                            const float* W0, int s0, int klim,
                            const float* W1, int s1) {
    for (int idx = threadIdx.x; idx < pairs; idx += 256) {
        int s = idx & 1, lane = (idx >> 1) & 31;
        int nb = (idx >> 6) & 3, ktG = idx >> 8;
        int gid = lane >> 2, tig = lane & 3;
        int n = nb * 8 + gid, k = ktG * 16 + tig * 2 + s * 8;
        const float* src; int kk;
        if (k < klim) { src = W0 + n * s0; kk = k; }
        else { src = W1 + n * s1; kk = k - klim; }
        float w0 = src[kk], w1 = src[kk + 1];
        float h0 = bfr(w0), h1 = bfr(w1);
        sm32[hiOff + idx] = pack2(h0, h1);
        sm32[loOff + idx] = pack2(w0 - h0, w1 - h1);
    }
}

// L2-only staging load (bypasses L1 -> always fresh across the barrier).
__device__ __forceinline__ void stage_ld(uint4& vh, uint4& vl,
                                         const uint32_t* hp, const uint32_t* lp,
                                         int off0, int off1) {
    int tid = threadIdx.x;
    int off = ((tid >> 7) ? off1 : off0) + (tid & 127) * 4;
    vh = __ldcg((const uint4*)(hp + off));
    vl = __ldcg((const uint4*)(lp + off));
}
__device__ __forceinline__ void stage_st(uint32_t* sm, int bufIdx,
                                         uint4 vh, uint4 vl) {
    int tid = threadIdx.x;
    uint32_t* d = sm + ACT + bufIdx * 2048 + (tid >> 7) * 512 + (tid & 127) * 4;
    *(uint4*)d = vh;
    *(uint4*)(d + 1024) = vl;
}

// 4 k16-tiles of one staged chunk with EVEN/ODD accumulator split.
__device__ __forceinline__ void mma_chunk(float* accE, float* accO,
                                          const uint32_t* smact,
                                          const uint32_t* whi, const uint32_t* wlo,
                                          int ktG0, int rb, int nb, int lane) {
#pragma unroll
    for (int ktl = 0; ktl < 4; ktl++) {
        const uint32_t* a = smact + (rb * 4 + ktl) * 128 + lane * 4;
        uint4 ah = *(const uint4*)a;
        uint4 al = *(const uint4*)(a + 1024);
        int widx = (ktG0 + ktl) * 4 + nb;
        uint2 bh = *(const uint2*)(whi + (widx * 32 + lane) * 2);
        uint2 bl = *(const uint2*)(wlo + (widx * 32 + lane) * 2);
        float* d = (ktl & 1) ? accO : accE;
        mmaw(d, ah, bh);
        mmaw(d, ah, bl);
        mmaw(d, al, bh);
    }
}

// Merged-interval persistent scan; per-row-block barriers; 2-deep prefetch
// via SCALAR register pairs + unroll-2 (no dynamically-indexed arrays).
__global__ __launch_bounds__(256, 1) void k_scan(
    const float* __restrict__ x, const float* __restrict__ Win0,
    const float* __restrict__ bin0, const float* __restrict__ A0,
    const float* __restrict__ tau0, const float* __restrict__ Win1,
    const float* __restrict__ bin1, const float* __restrict__ A1,
    const float* __restrict__ tau1, const float* __restrict__ Wout,
    const float* __restrict__ bout, float* __restrict__ out) {
    extern __shared__ uint32_t sm[];
    float* miscf = (float*)(sm + MISC);
    const int tid = threadIdx.x, bx = blockIdx.x;
    const int w = tid >> 5, lane = tid & 31;
    const int gid = lane >> 2, tig = lane & 3;
    const int rb = w & 1, nb = w >> 1;
    const bool is_main = (bx < 128);
    int row0, col0;
    if (is_main) { row0 = (bx >> 4) * 32; col0 = (bx & 15) * 32; }
    else { int idx = bx - 128; row0 = (idx >> 1) * 32; col0 = (idx & 1) * 32; }
    const int grp = row0 >> 5;  // row-block group id (0..7)

    if (is_main) {
        stage_wfrag(sm, WA_HI, WA_LO, 9216, A0 + col0 * H, H, 512,
                    Win0 + col0 * I, I);
        stage_wfrag(sm, WB_HI, WB_LO, 16384, Win1 + col0 * H, H, 512,
                    A1 + col0 * H, H);
        if (tid < 32) {
            miscf[tid] = bin0[col0 + tid];
            miscf[32 + tid] = 1.0f / (fabsf(tau0[col0 + tid]) + EPS_TAU);
            miscf[64 + tid] = bin1[col0 + tid];
            miscf[96 + tid] = 1.0f / (fabsf(tau1[col0 + tid]) + EPS_TAU);
        }
    } else {
        stage_wfrag(sm, 0, 8192, 8192, Wout + col0 * H, H, 1 << 20, Wout, H);
        if (tid < 32) miscf[tid] = bout[col0 + tid];
    }
    __syncthreads();

    const int g = row0 + rb * 16 + gid;
    const int gc = col0 + nb * 8 + tig * 2;
    const int ci = nb * 8 + tig * 2;
    const int kpw = gc >> 1;
    const int rbg0 = row0 >> 4;
    const int wrbg = rbg0 + rb;
    const int widxh = ((wrbg * NKT + (kpw >> 3)) * 32 + gid * 4 + (kpw & 3)) * 4 +
                      ((kpw >> 2) & 1) * 2;
    const int oh0 = rbg0 * NKT * 128, oh1 = (rbg0 + 1) * NKT * 128;

    float hp0[4] = {0.f, 0.f, 0.f, 0.f};
    float hp1[4] = {0.f, 0.f, 0.f, 0.f};
    unsigned epoch = 0;

    for (int t = 0; t < T + 2; t++) {
        const int prh0 = (t - 1) & 1;  // h0(t-1)
        const int pwh0 = t & 1;        // h0(t)
        const int prh1 = t & 1;        // h1(t-2)
        const int pwh1 = (t - 1) & 1;  // h1(t-1)
        const bool doA = (t < T), doB = (t >= 1 && t <= T);

        if (is_main) {
            if (doA || doB) {
                const uint32_t* h0h = g_h0hi[prh0];
                const uint32_t* h0l = g_h0lo[prh0];
                const uint32_t* h1h = g_h1hi[prh1];
                const uint32_t* h1l = g_h1lo[prh1];
                const int tx = doA ? t : 0;
                const int ox0 = (rbg0 * T + tx) * 512, ox1 = ((rbg0 + 1) * T + tx) * 512;
                float accAE[4] = {0.f, 0.f, 0.f, 0.f};
                float accAO[4] = {0.f, 0.f, 0.f, 0.f};
                float accBE[4] = {0.f, 0.f, 0.f, 0.f};
                float accBO[4] = {0.f, 0.f, 0.f, 0.f};

                auto srcld = [&](uint4& vh, uint4& vl, int c) {
                    if (c < 8) stage_ld(vh, vl, h0h, h0l, oh0 + c * 512, oh1 + c * 512);
                    else if (c == 8) stage_ld(vh, vl, g_pxhi, g_pxlo, ox0, ox1);
                    else stage_ld(vh, vl, h1h, h1l, oh0 + (c - 9) * 512,
                                  oh1 + (c - 9) * 512);
                };
                auto do_mma = [&](int c, const uint32_t* ab) {
                    if (c < 8) {
                        if (doA) mma_chunk(accAE, accAO, ab, sm + WA_HI, sm + WA_LO,
                                           c * 4, rb, nb, lane);
                        if (doB) mma_chunk(accBE, accBO, ab, sm + WB_HI, sm + WB_LO,
                                           c * 4, rb, nb, lane);
                    } else if (c == 8) {
                        if (doA) mma_chunk(accAE, accAO, ab, sm + WA_HI, sm + WA_LO,
                                           32, rb, nb, lane);
                    } else {
                        if (doB) mma_chunk(accBE, accBO, ab, sm + WB_HI, sm + WB_LO,
                                           32 + (c - 9) * 4, rb, nb, lane);
                    }
                };
                auto epiA = [&]() {
                    float b0v = miscf[ci], b1v = miscf[ci + 1];
                    float i0 = miscf[32 + ci], i1 = miscf[32 + ci + 1];
                    float a0 = accAE[0] + accAO[0], a1 = accAE[1] + accAO[1];
                    float a2 = accAE[2] + accAO[2], a3 = accAE[3] + accAO[3];
                    hp0[0] += DT_STEP * i0 * (tanhf(a0 + b0v) - hp0[0]);
                    hp0[1] += DT_STEP * i1 * (tanhf(a1 + b1v) - hp0[1]);
                    hp0[2] += DT_STEP * i0 * (tanhf(a2 + b0v) - hp0[2]);
                    hp0[3] += DT_STEP * i1 * (tanhf(a3 + b1v) - hp0[3]);
                    uint2 u0 = packpair(hp0[0], hp0[1]);
                    uint2 u1 = packpair(hp0[2], hp0[3]);
                    *(uint2*)(g_h0hi[pwh0] + widxh) = make_uint2(u0.x, u1.x);
                    *(uint2*)(g_h0lo[pwh0] + widxh) = make_uint2(u0.y, u1.y);
                };

                uint4 vh0, vl0, vh1, vl1;  // scalar 2-deep prefetch registers
                srcld(vh0, vl0, 0);
                srcld(vh1, vl1, 1);
                stage_st(sm, 0, vh0, vl0);
#pragma unroll 1
                for (int cc = 0; cc < 17; cc += 2) {
                    // even chunk cc -> buffer 0
                    __syncthreads();
                    if (cc + 2 < 17) srcld(vh0, vl0, cc + 2);
                    do_mma(cc, sm + ACT);
                    if (cc + 1 < 17) stage_st(sm, 1, vh1, vl1);
                    if (cc == 8 && doA) epiA();  // overlap h0 store with B chunks
                    // odd chunk cc+1 -> buffer 1
                    if (cc + 1 >= 17) break;
                    __syncthreads();
                    if (cc + 3 < 17) srcld(vh1, vl1, cc + 3);
                    do_mma(cc + 1, sm + ACT + 2048);
                    if (cc + 2 < 17) stage_st(sm, 0, vh0, vl0);
                }
                if (doB) {
                    float b0v = miscf[64 + ci], b1v = miscf[64 + ci + 1];
                    float i0 = miscf[96 + ci], i1 = miscf[96 + ci + 1];
                    float a0 = accBE[0] + accBO[0], a1 = accBE[1] + accBO[1];
                    float a2 = accBE[2] + accBO[2], a3 = accBE[3] + accBO[3];
                    hp1[0] += DT_STEP * i0 * (tanhf(a0 + b0v) - hp1[0]);
                    hp1[1] += DT_STEP * i1 * (tanhf(a1 + b1v) - hp1[1]);
                    hp1[2] += DT_STEP * i0 * (tanhf(a2 + b0v) - hp1[2]);
                    hp1[3] += DT_STEP * i1 * (tanhf(a3 + b1v) - hp1[3]);
                    uint2 u0 = packpair(hp1[0], hp1[1]);
                    uint2 u1 = packpair(hp1[2], hp1[3]);
                    *(uint2*)(g_h1hi[pwh1] + widxh) = make_uint2(u0.x, u1.x);
                    *(uint2*)(g_h1lo[pwh1] + widxh) = make_uint2(u0.y, u1.y);
                }
            }
        } else if (t >= 2) {
            // y(t-2) = h1(t-2) @ Wout^T + bout
            const uint32_t* hp = g_h1hi[t & 1];
            const uint32_t* lp = g_h1lo[t & 1];
            float accE[4] = {0.f, 0.f, 0.f, 0.f};
            float accO[4] = {0.f, 0.f, 0.f, 0.f};
            uint4 vh0, vl0, vh1, vl1;
            stage_ld(vh0, vl0, hp, lp, oh0, oh1);
            stage_ld(vh1, vl1, hp, lp, oh0 + 512, oh1 + 512);
            stage_st(sm, 0, vh0, vl0);
#pragma unroll 1
            for (int cc = 0; cc < 8; cc += 2) {
                __syncthreads();
                if (cc + 2 < 8) stage_ld(vh0, vl0, hp, lp, oh0 + (cc + 2) * 512,
                                         oh1 + (cc + 2) * 512);
                mma_chunk(accE, accO, sm + ACT, sm + 0, sm + 8192,
                          cc * 4, rb, nb, lane);
                stage_st(sm, 1, vh1, vl1);
                __syncthreads();
                if (cc + 3 < 8) stage_ld(vh1, vl1, hp, lp, oh0 + (cc + 3) * 512,
                                         oh1 + (cc + 3) * 512);
                mma_chunk(accE, accO, sm + ACT + 2048, sm + 0, sm + 8192,
                          (cc + 1) * 4, rb, nb, lane);
                if (cc + 2 < 8) stage_st(sm, 0, vh0, vl0);
            }
            float b0v = miscf[ci], b1v = miscf[ci + 1];
            *(float2*)(out + g * (T * O) + (t - 2) * O + gc) =
                make_float2(accE[0] + accO[0] + b0v, accE[1] + accO[1] + b1v);
            *(float2*)(out + (g + 8) * (T * O) + (t - 2) * O + gc) =
                make_float2(accE[2] + accO[2] + b0v, accE[3] + accO[3] + b1v);
        }
        gsync(grp, epoch);
    }
}

extern "C" void kernel_launch(void* const* d_in, const int* in_sizes, int n_in,
                              void* d_out, int out_size) {
    const float* x    = (const float*)d_in[0];
    const float* Win0 = (const float*)d_in[1];
    const float* bin0 = (const float*)d_in[2];
    const float* A0   = (const float*)d_in[3];
    const float* tau0 = (const float*)d_in[4];
    const float* Win1 = (const float*)d_in[5];
    const float* bin1 = (const float*)d_in[6];
    const float* A1   = (const float*)d_in[7];
    const float* tau1 = (const float*)d_in[8];
    const float* Wout = (const float*)d_in[9];
    const float* bout = (const float*)d_in[10];
    float* out = (float*)d_out;

    cudaFuncSetAttribute(k_scan, cudaFuncAttributeMaxDynamicSharedMemorySize,
                         SMEM_BYTES);

    k_init<<<(HPLANE + 255) / 256, 256>>>();
    k_prep<<<512, 256>>>(x);
    k_scan<<<GRID, 256, SMEM_BYTES>>>(x, Win0, bin0, A0, tau0, Win1, bin1, A1,
                                      tau1, Wout, bout, out);
}

// round 15
// speedup vs baseline: 1.9285x; 1.0982x over previous
#include <cuda_runtime.h>
#include <cuda_bf16.h>
#include <math.h>
#include <stdint.h>

#define DT_STEP 0.1f
#define EPS_TAU 1e-6f

constexpr int B = 256, T = 512, I = 64, H = 512, O = 64;
constexpr int GRID = 144;   // 128 layer CTAs + 16 out-proj CTAs; all co-resident
constexpr int KP = H / 2;   // 256 kpairs per h row
constexpr int NKT = KP / 8; // 32 k16-tiles per h row
constexpr int GSZ = 18;     // CTAs per row-block group (16 main + 2 out)

// smem b32 offsets
constexpr int WA_HI = 0;        // 9216 (K=576)
constexpr int WA_LO = 9216;
constexpr int WB_HI = 18432;    // 16384 (K=1024)
constexpr int WB_LO = 34816;
constexpr int ACT = 51200;      // 2 bufs x (1024 hi + 1024 lo)
constexpr int MISC = ACT + 4096;
constexpr int REDA = MISC + 128;     // 1024 f32: A k-split partials
constexpr int REDB = REDA + 1024;    // 1024 f32: B k-split partials
constexpr int SMEM_BYTES = (REDB + 1024) * 4;  // 229,888 B (<= 232,448 cap)

// Global activation planes in MMA fragment order (round-8 layout).
constexpr int HPLANE = (B / 16) * NKT * 128;    // 65536 u32
constexpr int XPLANE = (B / 16) * T * 4 * 128;

__device__ uint32_t g_h0hi[2][HPLANE], g_h0lo[2][HPLANE];
__device__ uint32_t g_h1hi[2][HPLANE], g_h1lo[2][HPLANE];
__device__ uint32_t g_pxhi[XPLANE], g_pxlo[XPLANE];
__device__ unsigned g_arr[8 * 32];  // one barrier counter per row-block, 128B apart

__global__ void k_init() {
    int idx = blockIdx.x * blockDim.x + threadIdx.x;
    if (idx < HPLANE) {
        g_h0hi[0][idx] = 0u; g_h0hi[1][idx] = 0u;
        g_h0lo[0][idx] = 0u; g_h0lo[1][idx] = 0u;
        g_h1hi[0][idx] = 0u; g_h1hi[1][idx] = 0u;
        g_h1lo[0][idx] = 0u; g_h1lo[1][idx] = 0u;
    }
    if (idx < 8 * 32) g_arr[idx] = 0u;
}

__device__ __forceinline__ uint32_t pack2(float e0, float e1) {
    uint32_t r;  // low half = e0
    asm("cvt.rn.bf16x2.f32 %0, %1, %2;" : "=r"(r) : "f"(e1), "f"(e0));
    return r;
}
__device__ __forceinline__ float bfr(float x) {
    return __bfloat162float(__float2bfloat16_rn(x));
}
__device__ __forceinline__ uint2 packpair(float e0, float e1) {
    float h0 = bfr(e0), h1 = bfr(e1);
    return make_uint2(pack2(h0, h1), pack2(e0 - h0, e1 - h1));
}

// Pre-pack x into fragment-order planes.
__global__ void k_prep(const float* __restrict__ x) {
    int n = (B / 16) * T * 4 * 32;
    for (int i = blockIdx.x * blockDim.x + threadIdx.x; i < n;
         i += gridDim.x * blockDim.x) {
        int lane = i & 31, ktx = (i >> 5) & 3, t = (i >> 7) & (T - 1), rbg = i >> 16;
        int gid = lane >> 2, tigf = lane & 3;
        int kp0 = ktx * 8 + tigf;
        const float* xb = x + (size_t)(rbg * 16 + gid) * (T * I) + t * I;
        const float* xb8 = xb + 8 * (T * I);
        float2 v0 = *(const float2*)(xb + kp0 * 2);
        float2 v1 = *(const float2*)(xb8 + kp0 * 2);
        float2 v2 = *(const float2*)(xb + (kp0 + 4) * 2);
        float2 v3 = *(const float2*)(xb8 + (kp0 + 4) * 2);
        uint2 p0 = packpair(v0.x, v0.y), p1 = packpair(v1.x, v1.y);
        uint2 p2 = packpair(v2.x, v2.y), p3 = packpair(v3.x, v3.y);
        *(uint4*)(g_pxhi + i * 4) = make_uint4(p0.x, p1.x, p2.x, p3.x);
        *(uint4*)(g_pxlo + i * 4) = make_uint4(p0.y, p1.y, p2.y, p3.y);
    }
}

__device__ __forceinline__ void mmaw(float* d, uint4 a, uint2 b) {
    asm volatile(
        "mma.sync.aligned.m16n8k16.row.col.f32.bf16.bf16.f32 "
        "{%0,%1,%2,%3},{%4,%5,%6,%7},{%8,%9},{%0,%1,%2,%3};"
        : "+f"(d[0]), "+f"(d[1]), "+f"(d[2]), "+f"(d[3])
        : "r"(a.x), "r"(a.y), "r"(a.z), "r"(a.w), "r"(b.x), "r"(b.y));
}

// Per-row-block group barrier (18 CTAs). Staging loads bypass L1 (__ldcg),
// so only the PRE-barrier publish fence is needed.
__device__ __forceinline__ void gsync(int grp, unsigned& epoch) {
    epoch++;
    __syncthreads();
    __threadfence();
    if (threadIdx.x == 0) {
        atomicAdd(&g_arr[grp * 32], 1u);
        unsigned target = (unsigned)GSZ * epoch;
        while (*(volatile unsigned*)&g_arr[grp * 32] < target) {}
    }
    __syncthreads();
}

// One-time weight staging into fragment order.
__device__ void stage_wfrag(uint32_t* sm32, int hiOff, int loOff, int pairs,
                            const float* W0, int s0, int klim,
                            const float* W1, int s1) {
    for (int idx = threadIdx.x; idx < pairs; idx += 256) {
        int s = idx & 1, lane = (idx >> 1) & 31;
        int nb = (idx >> 6) & 3, ktG = idx >> 8;
        int gid = lane >> 2, tig = lane & 3;
        int n = nb * 8 + gid, k = ktG * 16 + tig * 2 + s * 8;
        const float* src; int kk;
        if (k < klim) { src = W0 + n * s0; kk = k; }
        else { src = W1 + n * s1; kk = k - klim; }
        float w0 = src[kk], w1 = src[kk + 1];
        float h0 = bfr(w0), h1 = bfr(w1);
        sm32[hiOff + idx] = pack2(h0, h1);
        sm32[loOff + idx] = pack2(w0 - h0, w1 - h1);
    }
}

// L2-only staging load.
__device__ __forceinline__ void stage_ld(uint4& vh, uint4& vl,
                                         const uint32_t* hp, const uint32_t* lp,
                                         int off0, int off1) {
    int tid = threadIdx.x;
    int off = ((tid >> 7) ? off1 : off0) + (tid & 127) * 4;
    vh = __ldcg((const uint4*)(hp + off));
    vl = __ldcg((const uint4*)(lp + off));
}
__device__ __forceinline__ void stage_st(uint32_t* sm, int bufIdx,
                                         uint4 vh, uint4 vl) {
    int tid = threadIdx.x;
    uint32_t* d = sm + ACT + bufIdx * 2048 + (tid >> 7) * 512 + (tid & 127) * 4;
    *(uint4*)d = vh;
    *(uint4*)(d + 1024) = vl;
}

// K-SPLIT chunk: this warp handles ktiles ks*2+{0,1} of the chunk, over its
// TWO n-blocks (nbp*2, nbp*2+1). acc[0..3] = nb even, acc[4..7] = nb odd.
__device__ __forceinline__ void mma_ks(float* acc, const uint32_t* smact,
                                       const uint32_t* whi, const uint32_t* wlo,
                                       int ktG0, int rb, int ks, int nbp, int lane) {
#pragma unroll
    for (int i = 0; i < 2; i++) {
        int ktl = ks * 2 + i;
        const uint32_t* a = smact + (rb * 4 + ktl) * 128 + lane * 4;
        uint4 ah = *(const uint4*)a;
        uint4 al = *(const uint4*)(a + 1024);
        int widx = (ktG0 + ktl) * 4 + nbp * 2;
        uint2 bh0 = *(const uint2*)(whi + (widx * 32 + lane) * 2);
        uint2 bl0 = *(const uint2*)(wlo + (widx * 32 + lane) * 2);
        uint2 bh1 = *(const uint2*)(whi + ((widx + 1) * 32 + lane) * 2);
        uint2 bl1 = *(const uint2*)(wlo + ((widx + 1) * 32 + lane) * 2);
        mmaw(acc, ah, bh0);
        mmaw(acc + 4, ah, bh1);
        mmaw(acc, ah, bl0);
        mmaw(acc + 4, ah, bl1);
        mmaw(acc, al, bh0);
        mmaw(acc + 4, al, bh1);
    }
}

// Non-split chunk (out-proj CTAs): rb=w&1, nb=w>>1, even/odd acc split.
__device__ __forceinline__ void mma_chunk(float* accE, float* accO,
                                          const uint32_t* smact,
                                          const uint32_t* whi, const uint32_t* wlo,
                                          int ktG0, int rb, int nb, int lane) {
#pragma unroll
    for (int ktl = 0; ktl < 4; ktl++) {
        const uint32_t* a = smact + (rb * 4 + ktl) * 128 + lane * 4;
        uint4 ah = *(const uint4*)a;
        uint4 al = *(const uint4*)(a + 1024);
        int widx = (ktG0 + ktl) * 4 + nb;
        uint2 bh = *(const uint2*)(whi + (widx * 32 + lane) * 2);
        uint2 bl = *(const uint2*)(wlo + (widx * 32 + lane) * 2);
        float* d = (ktl & 1) ? accO : accE;
        mmaw(d, ah, bh);
        mmaw(d, ah, bl);
        mmaw(d, al, bh);
    }
}

// Merged-interval persistent scan; per-row-block barriers; 2-deep prefetch;
// 2-WAY K-SPLIT warps (rb, nbp, ks) with reductions folded into chunk syncs.
__global__ __launch_bounds__(256, 1) void k_scan(
    const float* __restrict__ x, const float* __restrict__ Win0,
    const float* __restrict__ bin0, const float* __restrict__ A0,
    const float* __restrict__ tau0, const float* __restrict__ Win1,
    const float* __restrict__ bin1, const float* __restrict__ A1,
    const float* __restrict__ tau1, const float* __restrict__ Wout,
    const float* __restrict__ bout, float* __restrict__ out) {
    extern __shared__ uint32_t sm[];
    float* miscf = (float*)(sm + MISC);
    float* redA = (float*)(sm + REDA);
    float* redB = (float*)(sm + REDB);
    const int tid = threadIdx.x, bx = blockIdx.x;
    const int w = tid >> 5, lane = tid & 31;
    const int gid = lane >> 2, tig = lane & 3;
    const bool is_main = (bx < 128);
    int row0, col0;
    if (is_main) { row0 = (bx >> 4) * 32; col0 = (bx & 15) * 32; }
    else { int idx = bx - 128; row0 = (idx >> 1) * 32; col0 = (idx & 1) * 32; }
    const int grp = row0 >> 5;

    // main-CTA warp roles
    const int rb = w & 1, nbp = (w >> 1) & 1, ks = (w >> 2) & 1;
    // out-proj warp roles
    const int rbO = w & 1, nbO = w >> 1;

    if (is_main) {
        stage_wfrag(sm, WA_HI, WA_LO, 9216, A0 + col0 * H, H, 512,
                    Win0 + col0 * I, I);
        stage_wfrag(sm, WB_HI, WB_LO, 16384, Win1 + col0 * H, H, 512,
                    A1 + col0 * H, H);
        if (tid < 32) {
            miscf[tid] = bin0[col0 + tid];
            miscf[32 + tid] = 1.0f / (fabsf(tau0[col0 + tid]) + EPS_TAU);
            miscf[64 + tid] = bin1[col0 + tid];
            miscf[96 + tid] = 1.0f / (fabsf(tau1[col0 + tid]) + EPS_TAU);
        }
    } else {
        stage_wfrag(sm, 0, 8192, 8192, Wout + col0 * H, H, 1 << 20, Wout, H);
        if (tid < 32) miscf[tid] = bout[col0 + tid];
    }
    __syncthreads();

    const int rbg0 = row0 >> 4;
    const int oh0 = rbg0 * NKT * 128, oh1 = (rbg0 + 1) * NKT * 128;

    // epilogue geometry (main: rb/nbp/nbi; out: rbO/nbO)
    const int gM = row0 + rb * 16 + gid;
    const int wrbgM = rbg0 + rb;
    int ciN[2], widxN[2];
#pragma unroll
    for (int nbi = 0; nbi < 2; nbi++) {
        int ci_ = (nbp * 2 + nbi) * 8 + tig * 2;
        int kpw = (col0 + ci_) >> 1;
        ciN[nbi] = ci_;
        widxN[nbi] = ((wrbgM * NKT + (kpw >> 3)) * 32 + gid * 4 + (kpw & 3)) * 4 +
                     ((kpw >> 2) & 1) * 2;
    }
    const int gO = row0 + rbO * 16 + gid;
    const int gcO = col0 + nbO * 8 + tig * 2;
    const int ciO = nbO * 8 + tig * 2;
    const int redIdx = ((w & 3) * 32 + lane) * 8;

    float hp0[8], hp1[8];
#pragma unroll
    for (int i = 0; i < 8; i++) { hp0[i] = 0.f; hp1[i] = 0.f; }
    unsigned epoch = 0;

    for (int t = 0; t < T + 2; t++) {
        const int prh0 = (t - 1) & 1, pwh0 = t & 1;
        const int prh1 = t & 1, pwh1 = (t - 1) & 1;
        const bool doA = (t < T), doB = (t >= 1 && t <= T);

        if (is_main) {
            if (doA || doB) {
                const uint32_t* h0h = g_h0hi[prh0];
                const uint32_t* h0l = g_h0lo[prh0];
                const uint32_t* h1h = g_h1hi[prh1];
                const uint32_t* h1l = g_h1lo[prh1];
                const int tx = doA ? t : 0;
                const int ox0 = (rbg0 * T + tx) * 512, ox1 = ((rbg0 + 1) * T + tx) * 512;
                float accA[8], accB[8];
#pragma unroll
                for (int i = 0; i < 8; i++) { accA[i] = 0.f; accB[i] = 0.f; }

                auto srcld = [&](uint4& vh, uint4& vl, int c) {
                    if (c < 8) stage_ld(vh, vl, h0h, h0l, oh0 + c * 512, oh1 + c * 512);
                    else if (c == 8) stage_ld(vh, vl, g_pxhi, g_pxlo, ox0, ox1);
                    else stage_ld(vh, vl, h1h, h1l, oh0 + (c - 9) * 512,
                                  oh1 + (c - 9) * 512);
                };
                auto do_mma = [&](int c, const uint32_t* ab) {
                    if (c < 8) {
                        if (doA) mma_ks(accA, ab, sm + WA_HI, sm + WA_LO, c * 4,
                                        rb, ks, nbp, lane);
                        if (doB) mma_ks(accB, ab, sm + WB_HI, sm + WB_LO, c * 4,
                                        rb, ks, nbp, lane);
                    } else if (c == 8) {
                        if (doA) mma_ks(accA, ab, sm + WA_HI, sm + WA_LO, 32,
                                        rb, ks, nbp, lane);
                    } else {
                        if (doB) mma_ks(accB, ab, sm + WB_HI, sm + WB_LO,
                                        32 + (c - 9) * 4, rb, ks, nbp, lane);
                    }
                };
                // ks=0 epilogue helpers (read RED partials + finish h update)
                auto epiA = [&]() {
                    float f[8];
#pragma unroll
                    for (int j = 0; j < 8; j++) f[j] = accA[j] + redA[redIdx + j];
#pragma unroll
                    for (int nbi = 0; nbi < 2; nbi++) {
                        int ci_ = ciN[nbi];
                        float b0v = miscf[ci_], b1v = miscf[ci_ + 1];
                        float i0 = miscf[32 + ci_], i1 = miscf[32 + ci_ + 1];
                        float* h = hp0 + nbi * 4;
                        const float* fv = f + nbi * 4;
                        h[0] += DT_STEP * i0 * (tanhf(fv[0] + b0v) - h[0]);
                        h[1] += DT_STEP * i1 * (tanhf(fv[1] + b1v) - h[1]);
                        h[2] += DT_STEP * i0 * (tanhf(fv[2] + b0v) - h[2]);
                        h[3] += DT_STEP * i1 * (tanhf(fv[3] + b1v) - h[3]);
                        uint2 u0 = packpair(h[0], h[1]);
                        uint2 u1 = packpair(h[2], h[3]);
                        *(uint2*)(g_h0hi[pwh0] + widxN[nbi]) = make_uint2(u0.x, u1.x);
                        *(uint2*)(g_h0lo[pwh0] + widxN[nbi]) = make_uint2(u0.y, u1.y);
                    }
                };

                uint4 vh0, vl0, vh1, vl1;
                srcld(vh0, vl0, 0);
                srcld(vh1, vl1, 1);
                stage_st(sm, 0, vh0, vl0);
#pragma unroll 1
                for (int cc = 0; cc < 17; cc += 2) {
                    // even chunk cc -> buffer 0
                    __syncthreads();
                    if (cc + 2 < 17) srcld(vh0, vl0, cc + 2);
                    do_mma(cc, sm + ACT);
                    if (cc + 1 < 17) stage_st(sm, 1, vh1, vl1);
                    if (cc == 8 && doA && ks == 1) {
                        // ks=1 publishes A partials; consumed after next sync
                        float* wp = redA + redIdx;
                        *(float4*)wp = make_float4(accA[0], accA[1], accA[2], accA[3]);
                        *(float4*)(wp + 4) =
                            make_float4(accA[4], accA[5], accA[6], accA[7]);
                    }
                    if (cc + 1 >= 17) break;
                    // odd chunk cc+1 -> buffer 1
                    __syncthreads();
                    if (cc + 3 < 17) srcld(vh1, vl1, cc + 3);
                    do_mma(cc + 1, sm + ACT + 2048);
                    if (cc + 2 < 17) stage_st(sm, 0, vh0, vl0);
                    if (cc + 1 == 9 && doA && ks == 0) epiA();
                }
                if (doB) {
                    if (ks == 1) {
                        float* wp = redB + redIdx;
                        *(float4*)wp = make_float4(accB[0], accB[1], accB[2], accB[3]);
                        *(float4*)(wp + 4) =
                            make_float4(accB[4], accB[5], accB[6], accB[7]);
                    }
                    __syncthreads();
                    if (ks == 0) {
                        float f[8];
#pragma unroll
                        for (int j = 0; j < 8; j++) f[j] = accB[j] + redB[redIdx + j];
#pragma unroll
                        for (int nbi = 0; nbi < 2; nbi++) {
                            int ci_ = ciN[nbi];
                            float b0v = miscf[64 + ci_], b1v = miscf[64 + ci_ + 1];
                            float i0 = miscf[96 + ci_], i1 = miscf[96 + ci_ + 1];
                            float* h = hp1 + nbi * 4;
                            const float* fv = f + nbi * 4;
                            h[0] += DT_STEP * i0 * (tanhf(fv[0] + b0v) - h[0]);
                            h[1] += DT_STEP * i1 * (tanhf(fv[1] + b1v) - h[1]);
                            h[2] += DT_STEP * i0 * (tanhf(fv[2] + b0v) - h[2]);
                            h[3] += DT_STEP * i1 * (tanhf(fv[3] + b1v) - h[3]);
                            uint2 u0 = packpair(h[0], h[1]);
                            uint2 u1 = packpair(h[2], h[3]);
                            *(uint2*)(g_h1hi[pwh1] + widxN[nbi]) =
                                make_uint2(u0.x, u1.x);
                            *(uint2*)(g_h1lo[pwh1] + widxN[nbi]) =
                                make_uint2(u0.y, u1.y);
                        }
                    }
                }
            }
        } else if (t >= 2) {
            // y(t-2) = h1(t-2) @ Wout^T + bout (non-split path)
            const uint32_t* hp = g_h1hi[t & 1];
            const uint32_t* lp = g_h1lo[t & 1];
            float accE[4] = {0.f, 0.f, 0.f, 0.f};
            float accO[4] = {0.f, 0.f, 0.f, 0.f};
            uint4 vh0, vl0, vh1, vl1;
            stage_ld(vh0, vl0, hp, lp, oh0, oh1);
            stage_ld(vh1, vl1, hp, lp, oh0 + 512, oh1 + 512);
            stage_st(sm, 0, vh0, vl0);
#pragma unroll 1
            for (int cc = 0; cc < 8; cc += 2) {
                __syncthreads();
                if (cc + 2 < 8) stage_ld(vh0, vl0, hp, lp, oh0 + (cc + 2) * 512,
                                         oh1 + (cc + 2) * 512);
                mma_chunk(accE, accO, sm + ACT, sm + 0, sm + 8192,
                          cc * 4, rbO, nbO, lane);
                stage_st(sm, 1, vh1, vl1);
                __syncthreads();
                if (cc + 3 < 8) stage_ld(vh1, vl1, hp, lp, oh0 + (cc + 3) * 512,
                                         oh1 + (cc + 3) * 512);
                mma_chunk(accE, accO, sm + ACT + 2048, sm + 0, sm + 8192,
                          (cc + 1) * 4, rbO, nbO, lane);
                if (cc + 2 < 8) stage_st(sm, 0, vh0, vl0);
            }
            float b0v = miscf[ciO], b1v = miscf[ciO + 1];
            *(float2*)(out + gO * (T * O) + (t - 2) * O + gcO) =
                make_float2(accE[0] + accO[0] + b0v, accE[1] + accO[1] + b1v);
            *(float2*)(out + (gO + 8) * (T * O) + (t - 2) * O + gcO) =
                make_float2(accE[2] + accO[2] + b0v, accE[3] + accO[3] + b1v);
        }
        gsync(grp, epoch);
    }
}

extern "C" void kernel_launch(void* const* d_in, const int* in_sizes, int n_in,
                              void* d_out, int out_size) {
    const float* x    = (const float*)d_in[0];
    const float* Win0 = (const float*)d_in[1];
    const float* bin0 = (const float*)d_in[2];
    const float* A0   = (const float*)d_in[3];
    const float* tau0 = (const float*)d_in[4];
    const float* Win1 = (const float*)d_in[5];
    const float* bin1 = (const float*)d_in[6];
    const float* A1   = (const float*)d_in[7];
    const float* tau1 = (const float*)d_in[8];
    const float* Wout = (const float*)d_in[9];
    const float* bout = (const float*)d_in[10];
    float* out = (float*)d_out;

    cudaFuncSetAttribute(k_scan, cudaFuncAttributeMaxDynamicSharedMemorySize,
                         SMEM_BYTES);

    k_init<<<(HPLANE + 255) / 256, 256>>>();
    k_prep<<<512, 256>>>(x);
    k_scan<<<GRID, 256, SMEM_BYTES>>>(x, Win0, bin0, A0, tau0, Win1, bin1, A1,
                                      tau1, Wout, bout, out);
}